// round 10
// baseline (speedup 1.0000x reference)
#include <cuda_runtime.h>
#include <cuda_bf16.h>

// Problem dims
#define Bn   128
#define En   1024
#define Kn   64
#define HDn  256
#define ROWSn (7*HDn)   // 1792

// Decomposition: 8 batch-groups x 16 dim-groups = 128 persistent CTAs
#define NB_G 8
#define ND_G 16
#define NCTA (NB_G*ND_G)
#define BT   16          // batches per CTA
#define DTI  16          // hidden dims per CTA
#define NTHREADS 256
#define VWP  260         // padded k-stride (bank-conflict mitigation)

// smem layout (floats)
#define VW_OFF   0
#define HT_OFF   (112*VWP)                 // 29120
#define LW_OFF   (HT_OFF + BT*VWP)         // 33280
#define SC_OFF   (LW_OFF + 4*VWP)          // 34320
#define OUT_OFF  (SC_OFF + 4)              // 34324 (16B aligned)
#define HTO_OFF  (OUT_OFF + 4*BT*DTI)      // 35348
#define MS_OFF   (HTO_OFF + BT*DTI)        // 35604
#define SMEM_FLOATS (MS_OFF + BT)          // 35620
#define SMEM_BYTES  (SMEM_FLOATS*4)        // 142480

// scratch (static __device__ arrays: no allocation allowed)
__device__ int      g_ev[Bn*En];
__device__ float    g_G[Kn*ROWSn];
__device__ float    g_ht[2][Bn*HDn];
__device__ unsigned g_bar_count;
__device__ unsigned g_bar_gen;
__device__ int      g_mask_mode;   // 0=uint8, 1=int32, 2=float32

__device__ __forceinline__ float sigf(float x) {
    return __fdividef(1.0f, 1.0f + __expf(-x));
}

__device__ __forceinline__ float4 ldcg4(const float* p) {
    float4 v;
    asm volatile("ld.global.cg.v4.f32 {%0,%1,%2,%3},[%4];"
                 : "=f"(v.x),"=f"(v.y),"=f"(v.z),"=f"(v.w) : "l"(p));
    return v;
}
__device__ __forceinline__ void stcg4(float* p, float4 v) {
    asm volatile("st.global.cg.v4.f32 [%0],{%1,%2,%3,%4};"
                 :: "l"(p),"f"(v.x),"f"(v.y),"f"(v.z),"f"(v.w) : "memory");
}
// packed dual-fp32 FMA (Blackwell FFMA2) — only reachable via PTX
__device__ __forceinline__ void fma2(unsigned long long &acc,
                                     unsigned long long a, unsigned long long b) {
    asm("fma.rn.f32x2 %0,%1,%2,%0;" : "+l"(acc) : "l"(a), "l"(b));
}

// ---------------------------------------------------------------------------
// init: reset barrier + sniff mask dtype (first 256 elems of row0 are all true)
__global__ void k_init(const void* mask) {
    if (threadIdx.x == 0 && blockIdx.x == 0) {
        g_bar_count = 0u;
        g_bar_gen   = 0u;
        const float* mf = (const float*)mask;
        const int*   mi = (const int*)mask;
        bool okf = true, oki = true, anyf = false, anyi = false;
        for (int j = 0; j < 256; ++j) {
            float fv = mf[j];
            if (!(fv == 0.0f || fv == 1.0f)) okf = false;
            else if (fv == 1.0f) anyf = true;
            int iv = mi[j];
            if (!(iv == 0 || iv == 1)) oki = false;
            else if (iv == 1) anyi = true;
        }
        if      (okf && anyf) g_mask_mode = 2;
        else if (oki && anyi) g_mask_mode = 1;
        else                  g_mask_mode = 0;
    }
}

// one-hot -> index
__global__ void k_ev(const float* __restrict__ seq) {
    int idx = blockIdx.x * blockDim.x + threadIdx.x;   // b*En+e
    if (idx >= Bn*En) return;
    const float4* p = (const float4*)&seq[(size_t)idx * Kn];
    int kv = 0;
    #pragma unroll
    for (int j = 0; j < Kn/4; ++j) {
        float4 v = __ldg(&p[j]);
        if (v.x > 0.5f) kv = j*4;
        else if (v.y > 0.5f) kv = j*4+1;
        else if (v.z > 0.5f) kv = j*4+2;
        else if (v.w > 0.5f) kv = j*4+3;
    }
    g_ev[idx] = kv;
}

// bias table: G[k][r] = U_w[r][k] + U_b[r] + V_b[r]
__global__ void k_G(const float* __restrict__ U_w,
                    const float* __restrict__ U_b,
                    const float* __restrict__ V_b) {
    int idx = blockIdx.x * blockDim.x + threadIdx.x;
    if (idx >= Kn*ROWSn) return;
    int kv = idx / ROWSn;
    int r  = idx - kv * ROWSn;
    g_G[idx] = U_w[r*Kn + kv] + U_b[r] + V_b[r];
}

// ---------------------------------------------------------------------------
__device__ __forceinline__ void grid_barrier(unsigned want) {
    __syncthreads();
    if (threadIdx.x == 0) {
        __threadfence();
        unsigned t = atomicAdd(&g_bar_count, 1u);
        if (t == NCTA - 1) {
            atomicExch(&g_bar_count, 0u);
            __threadfence();
            atomicAdd(&g_bar_gen, 1u);
        } else {
            unsigned v;
            const unsigned* gp = &g_bar_gen;
            do {
                __nanosleep(64);
                asm volatile("ld.global.cg.u32 %0,[%1];" : "=r"(v) : "l"(gp));
            } while (v < want);
            __threadfence();
        }
    }
    __syncthreads();
}

// ---------------------------------------------------------------------------
__global__ void __launch_bounds__(NTHREADS, 1)
ctlstm_main(const void*  __restrict__ mask_raw,
            const float* __restrict__ times,
            const float* __restrict__ V_w,
            const float* __restrict__ Lw,
            const float* __restrict__ scale,
            float*       __restrict__ out)
{
    extern __shared__ float sm[];
    float* Vw_s    = sm + VW_OFF;
    float* ht_s    = sm + HT_OFF;
    float* Lw_s    = sm + LW_OFF;
    float* scale_s = sm + SC_OFF;
    float* out_s   = sm + OUT_OFF;
    float* htout_s = sm + HTO_OFF;
    float* m_s     = sm + MS_OFF;

    const int tid = threadIdx.x;
    const int cta = blockIdx.x;
    const int bg  = cta & (NB_G - 1);
    const int dg  = cta >> 3;
    const int b0  = bg * BT;
    const int d0  = dg * DTI;
    const int b_thr = tid & 15;
    const int d_thr = tid >> 4;
    const int bgl = b0 + b_thr;            // global batch of this thread's cell
    const int dgl = d0 + d_thr;            // global dim of this thread's cell
    const int k0  = dg * 4;                // lambda kappa base for this CTA
    const int mask_mode = g_mask_mode;

    // ---- load V_w slice (112 rows x 256) into padded smem -----------------
    for (int i = tid; i < 112 * (HDn/4); i += NTHREADS) {
        int row = i >> 6;                  // 0..111 == g*16 + dl
        int c4  = i & 63;
        int g   = row >> 4, dl = row & 15;
        float4 v = *(const float4*)&V_w[(size_t)(g*HDn + d0 + dl)*HDn + c4*4];
        float* dst = &Vw_s[row*VWP + c4*4];
        dst[0] = v.x; dst[1] = v.y; dst[2] = v.z; dst[3] = v.w;
    }
    // ---- Lw rows [k0, k0+4) + scale ----------------------------------------
    for (int i = tid; i < 4 * (HDn/4); i += NTHREADS) {
        int r = i >> 6, c4 = i & 63;
        float4 v = *(const float4*)&Lw[(size_t)(k0 + r)*HDn + c4*4];
        float* dst = &Lw_s[r*VWP + c4*4];
        dst[0] = v.x; dst[1] = v.y; dst[2] = v.z; dst[3] = v.w;
    }
    if (tid < 4) scale_s[tid] = scale[k0 + tid];
    // ---- ht_s = 0 (initial carry) ------------------------------------------
    for (int i = tid; i < BT*VWP; i += NTHREADS) ht_s[i] = 0.0f;
    __syncthreads();

    float ct  = 0.0f;   // cell state carry (this thread's (b,d) cell)
    float cb  = 0.0f;   // cbar carry
    float htr = 0.0f;   // hidden carry

    const float* hrow  = &ht_s[b_thr * VWP];
    const float* wbase = &Vw_s[d_thr * VWP];

    const size_t BEH  = (size_t)Bn * En * HDn;
    const size_t OFF1 = (size_t)Bn * En * Kn;   // after lambda block

    for (int e = 0; e < En; ++e) {
        // -------- per-step scalars (latency hidden under GEMM) -------------
        int kv = g_ev[bgl*En + e];
        float bias[7];
        #pragma unroll
        for (int g = 0; g < 7; ++g)
            bias[g] = __ldg(&g_G[(size_t)kv*ROWSn + g*HDn + dgl]);
        float mval;
        {
            int mi = bgl*En + e;
            if (mask_mode == 0)      mval = ((const unsigned char*)mask_raw)[mi] ? 1.0f : 0.0f;
            else if (mask_mode == 1) mval = ((const int*)mask_raw)[mi] ? 1.0f : 0.0f;
            else                     mval = (((const float*)mask_raw)[mi] != 0.0f) ? 1.0f : 0.0f;
        }
        float t0n = times[bgl*(En+1) + e];
        float t1n = times[bgl*(En+1) + e + 1];
        float dt  = t1n - t0n;
        if (d_thr == 0) m_s[b_thr] = mval;

        // -------- GEMM: nn[g] = dot(ht[b], Vw[g*256+dgl]) (FFMA2) ----------
        unsigned long long acc[7];
        #pragma unroll
        for (int g = 0; g < 7; ++g) acc[g] = 0ull;
        #pragma unroll 8
        for (int kk = 0; kk < HDn/4; ++kk) {
            ulonglong2 h = *reinterpret_cast<const ulonglong2*>(hrow + kk*4);
            #pragma unroll
            for (int g = 0; g < 7; ++g) {
                ulonglong2 w = *reinterpret_cast<const ulonglong2*>(
                                    wbase + g*(DTI*VWP) + kk*4);
                fma2(acc[g], h.x, w.x);
                fma2(acc[g], h.y, w.y);
            }
        }
        float nn[7];
        #pragma unroll
        for (int g = 0; g < 7; ++g) {
            float2 p = *reinterpret_cast<float2*>(&acc[g]);
            nn[g] = p.x + p.y + bias[g];
        }

        // -------- pointwise recurrence --------------------------------------
        float ig  = sigf(nn[0]);
        float fg  = sigf(nn[1]);
        float ib  = sigf(nn[2]);
        float fb  = sigf(nn[3]);
        float z   = 2.0f * sigf(nn[4]);
        float og  = sigf(nn[5]);
        float x6  = nn[6];
        float delta = (x6 > 20.0f) ? x6 : log1pf(__expf(x6));   // softplus
        float clow = fg*ct + ig*z;
        float cbn  = fb*cb + ib*z;
        float ctn  = cbn + (clow - cbn) * __expf(-dt*delta);
        float htn  = og * (2.0f*sigf(2.0f*ctn) - 1.0f);
        if (mval != 0.0f) { ct = ctn; cb = cbn; htr = htn; }

        // -------- stage outputs + ht for coalesced stores -------------------
        int cell = b_thr*DTI + d_thr;
        out_s[0*BT*DTI + cell] = mval * clow;
        out_s[1*BT*DTI + cell] = mval * cbn;
        out_s[2*BT*DTI + cell] = mval * delta;
        out_s[3*BT*DTI + cell] = mval * og;
        htout_s[cell] = htr;
        __syncthreads();

        // outputs: CLows/Cbars/deltas/OutGates, 64B-aligned float4 segments
        {
            int a  = tid >> 6;             // 0..3
            int rr = tid & 63;
            int bb = rr >> 2, d4 = rr & 3;
            float4 v = *(float4*)&out_s[a*BT*DTI + bb*DTI + d4*4];
            float* dst = out + OFF1 + (size_t)a*BEH
                       + ((size_t)(b0 + bb)*En + e)*HDn + d0 + d4*4;
            *(float4*)dst = v;
        }
        // ht exchange write (L2-coherent, bypass L1)
        float* htbuf = g_ht[e & 1];
        if (tid < 64) {
            int bb = tid >> 2, d4 = tid & 3;
            float4 v = *(float4*)&htout_s[bb*DTI + d4*4];
            stcg4(&htbuf[(size_t)(b0 + bb)*HDn + d0 + d4*4], v);
        }

        grid_barrier((unsigned)(e + 1));

        // reload full ht for my batch rows (written by all dim-groups)
        for (int i = tid; i < BT*(HDn/4); i += NTHREADS) {
            int bb = i >> 6, c4 = i & 63;
            float4 v = ldcg4(&htbuf[(size_t)(b0 + bb)*HDn + c4*4]);
            *(float4*)&ht_s[bb*VWP + c4*4] = v;
        }
        __syncthreads();

        // -------- lambda: 16 b x 4 kappa per CTA -----------------------------
        if (tid < 64) {
            int bl = tid & 15, kl = tid >> 4;
            const float* hr = &ht_s[bl*VWP];
            const float* lr = &Lw_s[kl*VWP];
            unsigned long long a2 = 0ull;
            #pragma unroll 8
            for (int kk = 0; kk < HDn/4; ++kk) {
                ulonglong2 h = *reinterpret_cast<const ulonglong2*>(hr + kk*4);
                ulonglong2 l = *reinterpret_cast<const ulonglong2*>(lr + kk*4);
                fma2(a2, h.x, l.x);
                fma2(a2, h.y, l.y);
            }
            float2 p = *reinterpret_cast<float2*>(&a2);
            float lt = p.x + p.y;
            float s  = scale_s[kl];
            float xx = __fdividef(lt, s);
            float sp = (xx > 20.0f) ? xx : log1pf(__expf(xx));
            float lam = s * sp;
            out[((size_t)(b0 + bl)*En + e)*Kn + k0 + kl] = m_s[bl] * lam;
        }
        __syncthreads();   // protect m_s / ht_s for next step
    }
}

// ---------------------------------------------------------------------------
extern "C" void kernel_launch(void* const* d_in, const int* in_sizes, int n_in,
                              void* d_out, int out_size) {
    const float*         seq   = (const float*)d_in[0];
    const void*          mask  = d_in[1];
    const float*         times = (const float*)d_in[2];
    const float*         U_w   = (const float*)d_in[3];
    const float*         U_b   = (const float*)d_in[4];
    const float*         V_w   = (const float*)d_in[5];
    const float*         V_b   = (const float*)d_in[6];
    const float*         Lw    = (const float*)d_in[7];
    const float*         scale = (const float*)d_in[8];
    float* out = (float*)d_out;

    k_init<<<1, 32>>>(mask);
    k_ev<<<(Bn*En + 127)/128, 128>>>(seq);
    k_G<<<(Kn*ROWSn + 255)/256, 256>>>(U_w, U_b, V_b);

    cudaFuncSetAttribute(ctlstm_main,
                         cudaFuncAttributeMaxDynamicSharedMemorySize, SMEM_BYTES);
    ctlstm_main<<<NCTA, NTHREADS, SMEM_BYTES>>>(mask, times, V_w, Lw, scale, out);
}

// round 11
// speedup vs baseline: 1.2554x; 1.2554x over previous
#include <cuda_runtime.h>
#include <cuda_bf16.h>

// Problem dims
#define Bn   128
#define En   1024
#define Kn   64
#define HDn  256
#define ROWSn (7*HDn)   // 1792

// Decomposition: 8 batch-groups x 16 dim-groups = 128 persistent CTAs
#define NB_G 8
#define ND_G 16
#define NCTA (NB_G*ND_G)
#define BT   16          // batches per CTA
#define DTI  16          // hidden dims per CTA
#define NTHREADS 256

// smem strides (floats). Data is k-half packed: f2 = (x[k], x[k+128]), k in [0,128)
#define W2ST 258         // V_w / Lw row stride (floats) -> conflict-free w LDS.64
#define H2ST 260         // ht row stride (floats), 16B-aligned rows for float4 refill
#define REDB 114         // reduction b-stride (f2 cells)
#define REDSL (16*REDB)  // 1824 f2 per k-slice

// smem layout (float offsets)
#define W2_OFF  0                         // 112*258 = 28896
#define H2_OFF  (112*W2ST)                // 28896,  16*260 = 4160
#define LW_OFF  (H2_OFF + BT*H2ST)        // 33056,  4*258 = 1032
#define SC_OFF  (LW_OFF + 4*W2ST)         // 34088,  4
#define MS_OFF  (SC_OFF + 4)              // 34092,  16 (+pad)
#define OUT_OFF (MS_OFF + 20)             // 34112 (16B aligned), 1024
#define RED_OFF (OUT_OFF + 1024)          // 35136,  4*1824*2 = 14592
#define SMEM_FLOATS (RED_OFF + 4*REDSL*2) // 49728
#define SMEM_BYTES  (SMEM_FLOATS*4)       // 198912

// scratch (static __device__ arrays: no allocation allowed)
__device__ int      g_ev[Bn*En];
__device__ float    g_G[Kn*ROWSn];
// ht exchange, k-half packed: float idx = b*256 + kk*2 + lane (kk in [0,128))
__device__ __align__(16) float g_ht2[2][Bn*HDn];
__device__ unsigned g_barc[NB_G][32];
__device__ unsigned g_barg[NB_G][32];
__device__ int      g_mask_mode;   // 0=uint8, 1=int32, 2=float32

typedef unsigned long long ull;

__device__ __forceinline__ float sigf(float x) {
    return __fdividef(1.0f, 1.0f + __expf(-x));
}
__device__ __forceinline__ float4 ldcg4(const float* p) {
    float4 v;
    asm volatile("ld.global.cg.v4.f32 {%0,%1,%2,%3},[%4];"
                 : "=f"(v.x),"=f"(v.y),"=f"(v.z),"=f"(v.w) : "l"(p));
    return v;
}
__device__ __forceinline__ void stcg1(float* p, float v) {
    asm volatile("st.global.cg.f32 [%0],%1;" :: "l"(p),"f"(v) : "memory");
}
// packed dual-fp32 FMA (Blackwell FFMA2) — only reachable via PTX
__device__ __forceinline__ void fma2(ull &acc, ull a, ull b) {
    asm("fma.rn.f32x2 %0,%1,%2,%0;" : "+l"(acc) : "l"(a), "l"(b));
}

// ---------------------------------------------------------------------------
// init: reset barriers + sniff mask dtype (first 256 elems of row0 are all true)
__global__ void k_init(const void* mask) {
    if (threadIdx.x < NB_G) {
        g_barc[threadIdx.x][0] = 0u;
        g_barg[threadIdx.x][0] = 0u;
    }
    if (threadIdx.x == 0) {
        const float* mf = (const float*)mask;
        const int*   mi = (const int*)mask;
        bool okf = true, oki = true, anyf = false, anyi = false;
        for (int j = 0; j < 256; ++j) {
            float fv = mf[j];
            if (!(fv == 0.0f || fv == 1.0f)) okf = false;
            else if (fv == 1.0f) anyf = true;
            int iv = mi[j];
            if (!(iv == 0 || iv == 1)) oki = false;
            else if (iv == 1) anyi = true;
        }
        if      (okf && anyf) g_mask_mode = 2;
        else if (oki && anyi) g_mask_mode = 1;
        else                  g_mask_mode = 0;
    }
}

// one-hot -> index
__global__ void k_ev(const float* __restrict__ seq) {
    int idx = blockIdx.x * blockDim.x + threadIdx.x;   // b*En+e
    if (idx >= Bn*En) return;
    const float4* p = (const float4*)&seq[(size_t)idx * Kn];
    int kv = 0;
    #pragma unroll
    for (int j = 0; j < Kn/4; ++j) {
        float4 v = __ldg(&p[j]);
        if (v.x > 0.5f) kv = j*4;
        else if (v.y > 0.5f) kv = j*4+1;
        else if (v.z > 0.5f) kv = j*4+2;
        else if (v.w > 0.5f) kv = j*4+3;
    }
    g_ev[idx] = kv;
}

// bias table: G[k][r] = U_w[r][k] + U_b[r] + V_b[r]
__global__ void k_G(const float* __restrict__ U_w,
                    const float* __restrict__ U_b,
                    const float* __restrict__ V_b) {
    int idx = blockIdx.x * blockDim.x + threadIdx.x;
    if (idx >= Kn*ROWSn) return;
    int kv = idx / ROWSn;
    int r  = idx - kv * ROWSn;
    g_G[idx] = U_w[r*Kn + kv] + U_b[r] + V_b[r];
}

// ---------------------------------------------------------------------------
__device__ __forceinline__ void bg_barrier(int bg, unsigned want) {
    __syncthreads();
    if (threadIdx.x == 0) {
        __threadfence();
        unsigned t = atomicAdd(&g_barc[bg][0], 1u);
        if (t == ND_G - 1) {
            atomicExch(&g_barc[bg][0], 0u);
            __threadfence();
            atomicAdd(&g_barg[bg][0], 1u);
        } else {
            unsigned v;
            const unsigned* gp = &g_barg[bg][0];
            do {
                __nanosleep(32);
                asm volatile("ld.global.cg.u32 %0,[%1];" : "=r"(v) : "l"(gp));
            } while (v < want);
            __threadfence();
        }
    }
    __syncthreads();
}

// ---------------------------------------------------------------------------
__global__ void __launch_bounds__(NTHREADS, 1)
ctlstm_main(const void*  __restrict__ mask_raw,
            const float* __restrict__ times,
            const float* __restrict__ V_w,
            const float* __restrict__ Lw,
            const float* __restrict__ scale,
            float*       __restrict__ out)
{
    extern __shared__ float sm[];
    float* w2    = sm + W2_OFF;
    float* h2    = sm + H2_OFF;
    float* lw2   = sm + LW_OFF;
    float* sc_s  = sm + SC_OFF;
    float* m_s   = sm + MS_OFF;
    float* out_s = sm + OUT_OFF;
    float* red   = sm + RED_OFF;

    const int tid = threadIdx.x;
    const int cta = blockIdx.x;
    const int bg  = cta & (NB_G - 1);
    const int dg  = cta >> 3;
    const int b0  = bg * BT;
    const int d0  = dg * DTI;

    // pointwise / per-cell mapping
    const int pb  = tid >> 4;             // local batch
    const int pd  = tid & 15;             // local dim
    const int bgl = b0 + pb;
    const int dgl = d0 + pd;

    // GEMM mapping: 4 k-slices x 2 warps; 64 lanes/slice = 16 dims x 4 batch-quads
    const int warp = tid >> 5, lane = tid & 31;
    const int sl   = warp >> 1;            // k-slice 0..3
    const int L    = ((warp & 1) << 5) | lane;
    const int gd   = L & 15;               // dim within CTA
    const int bq   = L >> 4;               // batch quad 0..3 (batches 4bq..4bq+3)
    const int kk0  = sl * 32;

    // lambda mapping
    const int lb    = tid >> 4;            // batch
    const int kslot = tid & 15;

    const int mask_mode = g_mask_mode;

    // ---- prologue: pack V_w slice (k-halves) into smem ---------------------
    for (int i = tid; i < 112*128; i += NTHREADS) {
        int row = i >> 7, kk = i & 127;
        int g = row >> 4, dl = row & 15;
        const float* src = &V_w[(size_t)(g*HDn + d0 + dl)*HDn + kk];
        float2 v; v.x = __ldg(src); v.y = __ldg(src + 128);
        *(float2*)&w2[row*W2ST + kk*2] = v;
    }
    for (int i = tid; i < 4*128; i += NTHREADS) {
        int r = i >> 7, kk = i & 127;
        const float* src = &Lw[(size_t)(dg*4 + r)*HDn + kk];
        float2 v; v.x = __ldg(src); v.y = __ldg(src + 128);
        *(float2*)&lw2[r*W2ST + kk*2] = v;
    }
    if (tid < 4) sc_s[tid] = scale[dg*4 + tid];
    for (int i = tid; i < BT*H2ST; i += NTHREADS) h2[i] = 0.0f;
    __syncthreads();

    float ct = 0.0f, cb = 0.0f, htr = 0.0f;

    const size_t BEH  = (size_t)Bn * En * HDn;
    const size_t OFF1 = (size_t)Bn * En * Kn;
    const int    ln   = dg >> 3;                 // k-half lane for ht store
    const int    kkd  = (dg & 7)*16 + pd;        // packed-k slot for ht store

    const float* hb = &h2[(bq*4)*H2ST + kk0*2];
    const float* wb = &w2[gd*W2ST + kk0*2];

    for (int e = 0; e < En; ++e) {
        // -------- prefetch per-step scalars (hidden under GEMM) -------------
        int kv = g_ev[bgl*En + e];
        float bias[7];
        #pragma unroll
        for (int g = 0; g < 7; ++g)
            bias[g] = __ldg(&g_G[(size_t)kv*ROWSn + g*HDn + dgl]);
        float mval;
        {
            int mi = bgl*En + e;
            if (mask_mode == 0)      mval = ((const unsigned char*)mask_raw)[mi] ? 1.0f : 0.0f;
            else if (mask_mode == 1) mval = ((const int*)mask_raw)[mi] ? 1.0f : 0.0f;
            else                     mval = (((const float*)mask_raw)[mi] != 0.0f) ? 1.0f : 0.0f;
        }
        float dt = times[bgl*(En+1) + e + 1] - times[bgl*(En+1) + e];

        // -------- register-blocked GEMM: 4 batches x 7 gates per thread -----
        ull acc[4][7];
        #pragma unroll
        for (int j = 0; j < 4; ++j)
            #pragma unroll
            for (int g = 0; g < 7; ++g) acc[j][g] = 0ull;

        #pragma unroll 4
        for (int k = 0; k < 32; ++k) {
            ull hv[4];
            #pragma unroll
            for (int j = 0; j < 4; ++j)
                hv[j] = *(const ull*)&hb[j*H2ST + k*2];
            #pragma unroll
            for (int g = 0; g < 7; ++g) {
                ull wv = *(const ull*)&wb[g*(16*W2ST) + k*2];
                #pragma unroll
                for (int j = 0; j < 4; ++j) fma2(acc[j][g], hv[j], wv);
            }
        }
        // store k-slice partials
        #pragma unroll
        for (int j = 0; j < 4; ++j)
            #pragma unroll
            for (int g = 0; g < 7; ++g)
                *(ull*)&red[(sl*REDSL + (bq*4+j)*REDB + g*16 + gd)*2] = acc[j][g];
        __syncthreads();

        // -------- reduce + pointwise recurrence ------------------------------
        float nn[7];
        #pragma unroll
        for (int g = 0; g < 7; ++g) {
            float v = bias[g];
            #pragma unroll
            for (int ss = 0; ss < 4; ++ss) {
                float2 p = *(const float2*)&red[(ss*REDSL + pb*REDB + g*16 + pd)*2];
                v += p.x + p.y;
            }
            nn[g] = v;
        }
        float ig = sigf(nn[0]);
        float fg = sigf(nn[1]);
        float ib = sigf(nn[2]);
        float fb = sigf(nn[3]);
        float z  = 2.0f * sigf(nn[4]);
        float og = sigf(nn[5]);
        float x6 = nn[6];
        float delta = (x6 > 20.0f) ? x6 : log1pf(__expf(x6));   // softplus
        float clow = fg*ct + ig*z;
        float cbn  = fb*cb + ib*z;
        float ctn  = cbn + (clow - cbn) * __expf(-dt*delta);
        float htn  = og * (2.0f*sigf(2.0f*ctn) - 1.0f);
        if (mval != 0.0f) { ct = ctn; cb = cbn; htr = htn; }

        // stage outputs, publish ht
        int cell = pb*16 + pd;
        out_s[0*256 + cell] = mval * clow;
        out_s[1*256 + cell] = mval * cbn;
        out_s[2*256 + cell] = mval * delta;
        out_s[3*256 + cell] = mval * og;
        if (pd == 0) m_s[pb] = mval;
        float* htbuf = g_ht2[e & 1];
        stcg1(&htbuf[bgl*256 + kkd*2 + ln], htr);
        __syncthreads();

        // -------- output stores: 64B-aligned float4 segments ----------------
        {
            int a  = tid >> 6;
            int rr = tid & 63;
            int bb = rr >> 2, d4 = rr & 3;
            float4 v = *(float4*)&out_s[a*256 + bb*16 + d4*4];
            float* dst = out + OFF1 + (size_t)a*BEH
                       + ((size_t)(b0 + bb)*En + e)*HDn + d0 + d4*4;
            *(float4*)dst = v;
        }

        bg_barrier(bg, (unsigned)(e + 1));

        // -------- refill packed ht for my 16 batches -------------------------
        for (int i = tid; i < BT*64; i += NTHREADS) {
            int bb = i >> 6, c = i & 63;
            float4 v = ldcg4(&htbuf[(b0 + bb)*256 + c*4]);
            *(float4*)&h2[bb*H2ST + c*4] = v;
        }
        __syncthreads();

        // -------- lambda: all 8 warps, k-split + shuffle reduce ---------------
        {
            ull la[4] = {0ull, 0ull, 0ull, 0ull};
            const float* hr = &h2[lb*H2ST];
            #pragma unroll
            for (int i = 0; i < 8; ++i) {
                int kk = kslot + i*16;
                ull hv = *(const ull*)&hr[kk*2];
                #pragma unroll
                for (int kl = 0; kl < 4; ++kl) {
                    ull lv = *(const ull*)&lw2[kl*W2ST + kk*2];
                    fma2(la[kl], hv, lv);
                }
            }
            float lam[4];
            #pragma unroll
            for (int kl = 0; kl < 4; ++kl) {
                float2 p = *(float2*)&la[kl];
                #pragma unroll
                for (int off = 8; off > 0; off >>= 1) {
                    p.x += __shfl_xor_sync(0xFFFFFFFFu, p.x, off);
                    p.y += __shfl_xor_sync(0xFFFFFFFFu, p.y, off);
                }
                lam[kl] = p.x + p.y;
            }
            if (kslot == 0) {
                float mv = m_s[lb];
                float4 o4;
                float* o = &o4.x;
                #pragma unroll
                for (int kl = 0; kl < 4; ++kl) {
                    float s  = sc_s[kl];
                    float xx = __fdividef(lam[kl], s);
                    float sp = (xx > 20.0f) ? xx : log1pf(__expf(xx));
                    o[kl] = mv * (s * sp);
                }
                *(float4*)&out[((size_t)(b0 + lb)*En + e)*Kn + dg*4] = o4;
            }
        }
        __syncthreads();   // protect h2 / m_s / out_s for next step
    }
}

// ---------------------------------------------------------------------------
extern "C" void kernel_launch(void* const* d_in, const int* in_sizes, int n_in,
                              void* d_out, int out_size) {
    const float* seq   = (const float*)d_in[0];
    const void*  mask  = d_in[1];
    const float* times = (const float*)d_in[2];
    const float* U_w   = (const float*)d_in[3];
    const float* U_b   = (const float*)d_in[4];
    const float* V_w   = (const float*)d_in[5];
    const float* V_b   = (const float*)d_in[6];
    const float* Lw    = (const float*)d_in[7];
    const float* scale = (const float*)d_in[8];
    float* out = (float*)d_out;

    k_init<<<1, 32>>>(mask);
    k_ev<<<(Bn*En + 127)/128, 128>>>(seq);
    k_G<<<(Kn*ROWSn + 255)/256, 256>>>(U_w, U_b, V_b);

    cudaFuncSetAttribute(ctlstm_main,
                         cudaFuncAttributeMaxDynamicSharedMemorySize, SMEM_BYTES);
    ctlstm_main<<<NCTA, NTHREADS, SMEM_BYTES>>>(mask, times, V_w, Lw, scale, out);
}

// round 12
// speedup vs baseline: 1.2582x; 1.0023x over previous
#include <cuda_runtime.h>
#include <cuda_bf16.h>

// Problem dims
#define Bn   128
#define En   1024
#define Kn   64
#define HDn  256
#define ROWSn (7*HDn)   // 1792

// Decomposition: 8 batch-groups x 16 dim-groups = 128 persistent CTAs
#define NB_G 8
#define ND_G 16
#define NCTA (NB_G*ND_G)
#define BT   16          // batches per CTA
#define DTI  16          // hidden dims per CTA
#define NTHREADS 256

// smem strides (floats). Data is k-half packed: f2 = (x[k], x[k+128]), k in [0,128)
#define W2ST 258         // V_w / Lw row stride (floats) -> conflict-free w LDS.64
#define H2ST 260         // ht row stride (floats), 16B-aligned rows for float4 refill
#define REDB 114         // reduction b-stride (f2 cells)
#define REDSL (16*REDB)  // 1824 f2 per k-slice

// smem layout (float offsets)
#define W2_OFF  0                         // 112*258 = 28896
#define H2_OFF  (112*W2ST)                // 28896,  16*260 = 4160
#define LW_OFF  (H2_OFF + BT*H2ST)        // 33056,  4*258 = 1032
#define SC_OFF  (LW_OFF + 4*W2ST)         // 34088,  4
#define MS_OFF  (SC_OFF + 4)              // 34092,  16 (+pad)
#define OUT_OFF (MS_OFF + 20)             // 34112 (16B aligned), 1024
#define RED_OFF (OUT_OFF + 1024)          // 35136,  4*1824*2 = 14592
#define SMEM_FLOATS (RED_OFF + 4*REDSL*2) // 49728
#define SMEM_BYTES  (SMEM_FLOATS*4)       // 198912

// scratch (static __device__ arrays: no allocation allowed)
__device__ int      g_ev[Bn*En];
__device__ float    g_G[Kn*ROWSn];
// ht exchange, k-half packed: float idx = b*256 + kk*2 + lane (kk in [0,128))
__device__ __align__(16) float g_ht2[2][Bn*HDn];
__device__ unsigned g_barc[NB_G][32];
__device__ unsigned g_barg[NB_G][32];
__device__ int      g_mask_mode;   // 0=uint8, 1=int32, 2=float32

typedef unsigned long long ull;

__device__ __forceinline__ float sigf(float x) {
    return __fdividef(1.0f, 1.0f + __expf(-x));
}
__device__ __forceinline__ float4 ldcg4(const float* p) {
    float4 v;
    asm volatile("ld.global.cg.v4.f32 {%0,%1,%2,%3},[%4];"
                 : "=f"(v.x),"=f"(v.y),"=f"(v.z),"=f"(v.w) : "l"(p));
    return v;
}
__device__ __forceinline__ void stcg1(float* p, float v) {
    asm volatile("st.global.cg.f32 [%0],%1;" :: "l"(p),"f"(v) : "memory");
}
// packed dual-fp32 FMA (Blackwell FFMA2) — only reachable via PTX
__device__ __forceinline__ void fma2(ull &acc, ull a, ull b) {
    asm("fma.rn.f32x2 %0,%1,%2,%0;" : "+l"(acc) : "l"(a), "l"(b));
}

// ---------------------------------------------------------------------------
// init: reset barriers + sniff mask dtype (first 256 elems of row0 are all true)
__global__ void k_init(const void* mask) {
    if (threadIdx.x < NB_G) {
        g_barc[threadIdx.x][0] = 0u;
        g_barg[threadIdx.x][0] = 0u;
    }
    if (threadIdx.x == 0) {
        const float* mf = (const float*)mask;
        const int*   mi = (const int*)mask;
        bool okf = true, oki = true, anyf = false, anyi = false;
        for (int j = 0; j < 256; ++j) {
            float fv = mf[j];
            if (!(fv == 0.0f || fv == 1.0f)) okf = false;
            else if (fv == 1.0f) anyf = true;
            int iv = mi[j];
            if (!(iv == 0 || iv == 1)) oki = false;
            else if (iv == 1) anyi = true;
        }
        if      (okf && anyf) g_mask_mode = 2;
        else if (oki && anyi) g_mask_mode = 1;
        else                  g_mask_mode = 0;
    }
}

// one-hot -> index
__global__ void k_ev(const float* __restrict__ seq) {
    int idx = blockIdx.x * blockDim.x + threadIdx.x;   // b*En+e
    if (idx >= Bn*En) return;
    const float4* p = (const float4*)&seq[(size_t)idx * Kn];
    int kv = 0;
    #pragma unroll
    for (int j = 0; j < Kn/4; ++j) {
        float4 v = __ldg(&p[j]);
        if (v.x > 0.5f) kv = j*4;
        else if (v.y > 0.5f) kv = j*4+1;
        else if (v.z > 0.5f) kv = j*4+2;
        else if (v.w > 0.5f) kv = j*4+3;
    }
    g_ev[idx] = kv;
}

// bias table: G[k][r] = U_w[r][k] + U_b[r] + V_b[r]
__global__ void k_G(const float* __restrict__ U_w,
                    const float* __restrict__ U_b,
                    const float* __restrict__ V_b) {
    int idx = blockIdx.x * blockDim.x + threadIdx.x;
    if (idx >= Kn*ROWSn) return;
    int kv = idx / ROWSn;
    int r  = idx - kv * ROWSn;
    g_G[idx] = U_w[r*Kn + kv] + U_b[r] + V_b[r];
}

// ---------------------------------------------------------------------------
__device__ __forceinline__ void bg_barrier(int bg, unsigned want) {
    __syncthreads();
    if (threadIdx.x == 0) {
        __threadfence();
        unsigned t = atomicAdd(&g_barc[bg][0], 1u);
        if (t == ND_G - 1) {
            atomicExch(&g_barc[bg][0], 0u);
            __threadfence();
            atomicAdd(&g_barg[bg][0], 1u);
        } else {
            unsigned v;
            const unsigned* gp = &g_barg[bg][0];
            do {
                __nanosleep(32);
                asm volatile("ld.global.cg.u32 %0,[%1];" : "=r"(v) : "l"(gp));
            } while (v < want);
            __threadfence();
        }
    }
    __syncthreads();
}

// ---------------------------------------------------------------------------
__global__ void __launch_bounds__(NTHREADS, 1)
ctlstm_main(const void*  __restrict__ mask_raw,
            const float* __restrict__ times,
            const float* __restrict__ V_w,
            const float* __restrict__ Lw,
            const float* __restrict__ scale,
            float*       __restrict__ out)
{
    extern __shared__ float sm[];
    float* w2    = sm + W2_OFF;
    float* h2    = sm + H2_OFF;
    float* lw2   = sm + LW_OFF;
    float* sc_s  = sm + SC_OFF;
    float* m_s   = sm + MS_OFF;
    float* out_s = sm + OUT_OFF;
    float* red   = sm + RED_OFF;

    const int tid = threadIdx.x;
    const int cta = blockIdx.x;
    const int bg  = cta & (NB_G - 1);
    const int dg  = cta >> 3;
    const int b0  = bg * BT;
    const int d0  = dg * DTI;

    // pointwise / per-cell mapping
    const int pb  = tid >> 4;             // local batch
    const int pd  = tid & 15;             // local dim
    const int bgl = b0 + pb;
    const int dgl = d0 + pd;

    // GEMM mapping: 4 k-slices x 2 warps; 64 lanes/slice = 16 dims x 4 batch-quads
    const int warp = tid >> 5, lane = tid & 31;
    const int sl   = warp >> 1;            // k-slice 0..3
    const int L    = ((warp & 1) << 5) | lane;
    const int gd   = L & 15;               // dim within CTA
    const int bq   = L >> 4;               // batch quad 0..3 (batches 4bq..4bq+3)
    const int kk0  = sl * 32;

    // lambda mapping
    const int lb    = tid >> 4;            // batch
    const int kslot = tid & 15;

    const int mask_mode = g_mask_mode;

    // ---- prologue: pack V_w slice (k-halves) into smem ---------------------
    for (int i = tid; i < 112*128; i += NTHREADS) {
        int row = i >> 7, kk = i & 127;
        int g = row >> 4, dl = row & 15;
        const float* src = &V_w[(size_t)(g*HDn + d0 + dl)*HDn + kk];
        float2 v; v.x = __ldg(src); v.y = __ldg(src + 128);
        *(float2*)&w2[row*W2ST + kk*2] = v;
    }
    for (int i = tid; i < 4*128; i += NTHREADS) {
        int r = i >> 7, kk = i & 127;
        const float* src = &Lw[(size_t)(dg*4 + r)*HDn + kk];
        float2 v; v.x = __ldg(src); v.y = __ldg(src + 128);
        *(float2*)&lw2[r*W2ST + kk*2] = v;
    }
    if (tid < 4) sc_s[tid] = scale[dg*4 + tid];
    for (int i = tid; i < BT*H2ST; i += NTHREADS) h2[i] = 0.0f;
    __syncthreads();

    float ct = 0.0f, cb = 0.0f, htr = 0.0f;

    const size_t BEH  = (size_t)Bn * En * HDn;
    const size_t OFF1 = (size_t)Bn * En * Kn;
    const int    ln   = dg >> 3;                 // k-half lane for ht store
    const int    kkd  = (dg & 7)*16 + pd;        // packed-k slot for ht store

    const float* hb = &h2[(bq*4)*H2ST + kk0*2];
    const float* wb = &w2[gd*W2ST + kk0*2];

    for (int e = 0; e < En; ++e) {
        // -------- prefetch per-step scalars (hidden under GEMM) -------------
        int kv = g_ev[bgl*En + e];
        float bias[7];
        #pragma unroll
        for (int g = 0; g < 7; ++g)
            bias[g] = __ldg(&g_G[(size_t)kv*ROWSn + g*HDn + dgl]);
        float mval;
        {
            int mi = bgl*En + e;
            if (mask_mode == 0)      mval = ((const unsigned char*)mask_raw)[mi] ? 1.0f : 0.0f;
            else if (mask_mode == 1) mval = ((const int*)mask_raw)[mi] ? 1.0f : 0.0f;
            else                     mval = (((const float*)mask_raw)[mi] != 0.0f) ? 1.0f : 0.0f;
        }
        float dt = times[bgl*(En+1) + e + 1] - times[bgl*(En+1) + e];

        // -------- register-blocked GEMM: 4 batches x 7 gates per thread -----
        ull acc[4][7];
        #pragma unroll
        for (int j = 0; j < 4; ++j)
            #pragma unroll
            for (int g = 0; g < 7; ++g) acc[j][g] = 0ull;

        #pragma unroll 4
        for (int k = 0; k < 32; ++k) {
            ull hv[4];
            #pragma unroll
            for (int j = 0; j < 4; ++j)
                hv[j] = *(const ull*)&hb[j*H2ST + k*2];
            #pragma unroll
            for (int g = 0; g < 7; ++g) {
                ull wv = *(const ull*)&wb[g*(16*W2ST) + k*2];
                #pragma unroll
                for (int j = 0; j < 4; ++j) fma2(acc[j][g], hv[j], wv);
            }
        }
        // store k-slice partials
        #pragma unroll
        for (int j = 0; j < 4; ++j)
            #pragma unroll
            for (int g = 0; g < 7; ++g)
                *(ull*)&red[(sl*REDSL + (bq*4+j)*REDB + g*16 + gd)*2] = acc[j][g];
        __syncthreads();

        // -------- reduce + pointwise recurrence ------------------------------
        float nn[7];
        #pragma unroll
        for (int g = 0; g < 7; ++g) {
            float v = bias[g];
            #pragma unroll
            for (int ss = 0; ss < 4; ++ss) {
                float2 p = *(const float2*)&red[(ss*REDSL + pb*REDB + g*16 + pd)*2];
                v += p.x + p.y;
            }
            nn[g] = v;
        }
        float ig = sigf(nn[0]);
        float fg = sigf(nn[1]);
        float ib = sigf(nn[2]);
        float fb = sigf(nn[3]);
        float z  = 2.0f * sigf(nn[4]);
        float og = sigf(nn[5]);
        float x6 = nn[6];
        float delta = (x6 > 20.0f) ? x6 : log1pf(__expf(x6));   // softplus
        float clow = fg*ct + ig*z;
        float cbn  = fb*cb + ib*z;
        float ctn  = cbn + (clow - cbn) * __expf(-dt*delta);
        float htn  = og * (2.0f*sigf(2.0f*ctn) - 1.0f);
        if (mval != 0.0f) { ct = ctn; cb = cbn; htr = htn; }

        // stage outputs, publish ht
        int cell = pb*16 + pd;
        out_s[0*256 + cell] = mval * clow;
        out_s[1*256 + cell] = mval * cbn;
        out_s[2*256 + cell] = mval * delta;
        out_s[3*256 + cell] = mval * og;
        if (pd == 0) m_s[pb] = mval;
        float* htbuf = g_ht2[e & 1];
        stcg1(&htbuf[bgl*256 + kkd*2 + ln], htr);
        __syncthreads();

        // -------- output stores: 64B-aligned float4 segments ----------------
        {
            int a  = tid >> 6;
            int rr = tid & 63;
            int bb = rr >> 2, d4 = rr & 3;
            float4 v = *(float4*)&out_s[a*256 + bb*16 + d4*4];
            float* dst = out + OFF1 + (size_t)a*BEH
                       + ((size_t)(b0 + bb)*En + e)*HDn + d0 + d4*4;
            *(float4*)dst = v;
        }

        bg_barrier(bg, (unsigned)(e + 1));

        // -------- refill packed ht for my 16 batches -------------------------
        for (int i = tid; i < BT*64; i += NTHREADS) {
            int bb = i >> 6, c = i & 63;
            float4 v = ldcg4(&htbuf[(b0 + bb)*256 + c*4]);
            *(float4*)&h2[bb*H2ST + c*4] = v;
        }
        __syncthreads();

        // -------- lambda: all 8 warps, k-split + shuffle reduce ---------------
        {
            ull la[4] = {0ull, 0ull, 0ull, 0ull};
            const float* hr = &h2[lb*H2ST];
            #pragma unroll
            for (int i = 0; i < 8; ++i) {
                int kk = kslot + i*16;
                ull hv = *(const ull*)&hr[kk*2];
                #pragma unroll
                for (int kl = 0; kl < 4; ++kl) {
                    ull lv = *(const ull*)&lw2[kl*W2ST + kk*2];
                    fma2(la[kl], hv, lv);
                }
            }
            float lam[4];
            #pragma unroll
            for (int kl = 0; kl < 4; ++kl) {
                float2 p = *(float2*)&la[kl];
                #pragma unroll
                for (int off = 8; off > 0; off >>= 1) {
                    p.x += __shfl_xor_sync(0xFFFFFFFFu, p.x, off);
                    p.y += __shfl_xor_sync(0xFFFFFFFFu, p.y, off);
                }
                lam[kl] = p.x + p.y;
            }
            if (kslot == 0) {
                float mv = m_s[lb];
                float4 o4;
                float* o = &o4.x;
                #pragma unroll
                for (int kl = 0; kl < 4; ++kl) {
                    float s  = sc_s[kl];
                    float xx = __fdividef(lam[kl], s);
                    float sp = (xx > 20.0f) ? xx : log1pf(__expf(xx));
                    o[kl] = mv * (s * sp);
                }
                *(float4*)&out[((size_t)(b0 + lb)*En + e)*Kn + dg*4] = o4;
            }
        }
        __syncthreads();   // protect h2 / m_s / out_s for next step
    }
}

// ---------------------------------------------------------------------------
extern "C" void kernel_launch(void* const* d_in, const int* in_sizes, int n_in,
                              void* d_out, int out_size) {
    const float* seq   = (const float*)d_in[0];
    const void*  mask  = d_in[1];
    const float* times = (const float*)d_in[2];
    const float* U_w   = (const float*)d_in[3];
    const float* U_b   = (const float*)d_in[4];
    const float* V_w   = (const float*)d_in[5];
    const float* V_b   = (const float*)d_in[6];
    const float* Lw    = (const float*)d_in[7];
    const float* scale = (const float*)d_in[8];
    float* out = (float*)d_out;

    k_init<<<1, 32>>>(mask);
    k_ev<<<(Bn*En + 127)/128, 128>>>(seq);
    k_G<<<(Kn*ROWSn + 255)/256, 256>>>(U_w, U_b, V_b);

    cudaFuncSetAttribute(ctlstm_main,
                         cudaFuncAttributeMaxDynamicSharedMemorySize, SMEM_BYTES);
    ctlstm_main<<<NCTA, NTHREADS, SMEM_BYTES>>>(mask, times, V_w, Lw, scale, out);
}